// round 2
// baseline (speedup 1.0000x reference)
#include <cuda_runtime.h>
#include <cstdint>

// LinearTPReadOut: out[n] = w_tp/sqrt(3) * (1/128) * sum_i A_i(n)*B_i(n)
//   A_i(n) = sum_u x[n, 128+3u+i] * w_lin[u,0],  B_i likewise with w_lin[u,1]
// x: (N,1152) f32, w_lin: (128,2) f32, w_tp: (1,) f32, out: (N,) f32
//
// Dense-coalesced version: lane l reads float4 indices {l, l+32, l+64} of the
// 384-float active span -> every LDG.128 is 4 wavefronts (optimal).
// Channel bookkeeping via rotated accumulators:
//   float position e = 128j + 4l + c has i = e%3 = ((c+2j)%3 + l)%3,
//   so accumulate into rot[(c+2j)%3] (compile-time) and un-rotate by s=l%3.
// 8 rows per warp amortize the per-thread weight-register preload.

#define ROW_STRIDE_F   1152
#define ROW_STRIDE_V4  288          // 1152/4
#define COL_OFF        128
#define ROWS_PER_WARP  8

__global__ __launch_bounds__(256)
void lintp_kernel(const float* __restrict__ x,
                  const float* __restrict__ w_lin,
                  const float* __restrict__ w_tp,
                  float* __restrict__ out, int n)
{
    const int lane = threadIdx.x & 31;
    const int warpGlobal = (blockIdx.x * blockDim.x + threadIdx.x) >> 5;
    const int row0 = warpGlobal * ROWS_PER_WARP;
    if (row0 >= n) return;

    // ---- per-thread weight preload (amortized over ROWS_PER_WARP rows) ----
    // For load j, lane's float4 covers positions e..e+3, e = 128j+4*lane.
    // u = e/3 spans {u0, u0+1}; select per c at preload time.
    float wa[3][4], wb[3][4];
    const float2* wp = reinterpret_cast<const float2*>(w_lin);  // (w0[u], w1[u])
    #pragma unroll
    for (int j = 0; j < 3; j++) {
        const int e  = 128 * j + 4 * lane;
        const int u0 = e / 3;
        const int pm = e - 3 * u0;
        const float2 p0 = __ldg(wp + u0);
        const float2 p1 = __ldg(wp + u0 + 1);
        #pragma unroll
        for (int c = 0; c < 4; c++) {
            const bool hi = (pm + c) >= 3;
            wa[j][c] = hi ? p1.x : p0.x;
            wb[j][c] = hi ? p1.y : p0.y;
        }
    }
    const float scale = __ldg(w_tp) * 0.57735026918962576451f * (1.0f / 128.0f);
    const int s = lane % 3;

    const float4* xbase = reinterpret_cast<const float4*>(
        x + (size_t)row0 * ROW_STRIDE_F + COL_OFF) + lane;

    #pragma unroll 4
    for (int r = 0; r < ROWS_PER_WARP; r++) {
        const int row = row0 + r;
        if (row >= n) break;                       // warp-uniform
        const float4* xp = xbase + (size_t)r * ROW_STRIDE_V4;
        float4 v0 = xp[0];
        float4 v1 = xp[32];
        float4 v2 = xp[64];

        float rA0 = 0.f, rA1 = 0.f, rA2 = 0.f;
        float rB0 = 0.f, rB1 = 0.f, rB2 = 0.f;
        {
            // j=0: k = c%3 -> 0,1,2,0
            rA0 = fmaf(v0.x, wa[0][0], rA0);  rB0 = fmaf(v0.x, wb[0][0], rB0);
            rA1 = fmaf(v0.y, wa[0][1], rA1);  rB1 = fmaf(v0.y, wb[0][1], rB1);
            rA2 = fmaf(v0.z, wa[0][2], rA2);  rB2 = fmaf(v0.z, wb[0][2], rB2);
            rA0 = fmaf(v0.w, wa[0][3], rA0);  rB0 = fmaf(v0.w, wb[0][3], rB0);
            // j=1: k = (c+2)%3 -> 2,0,1,2
            rA2 = fmaf(v1.x, wa[1][0], rA2);  rB2 = fmaf(v1.x, wb[1][0], rB2);
            rA0 = fmaf(v1.y, wa[1][1], rA0);  rB0 = fmaf(v1.y, wb[1][1], rB0);
            rA1 = fmaf(v1.z, wa[1][2], rA1);  rB1 = fmaf(v1.z, wb[1][2], rB1);
            rA2 = fmaf(v1.w, wa[1][3], rA2);  rB2 = fmaf(v1.w, wb[1][3], rB2);
            // j=2: k = (c+4)%3 -> 1,2,0,1
            rA1 = fmaf(v2.x, wa[2][0], rA1);  rB1 = fmaf(v2.x, wb[2][0], rB1);
            rA2 = fmaf(v2.y, wa[2][1], rA2);  rB2 = fmaf(v2.y, wb[2][1], rB2);
            rA0 = fmaf(v2.z, wa[2][2], rA0);  rB0 = fmaf(v2.z, wb[2][2], rB0);
            rA1 = fmaf(v2.w, wa[2][3], rA1);  rB1 = fmaf(v2.w, wb[2][3], rB1);
        }

        // un-rotate: absolute A_i = rot[(i - s) mod 3]
        float A0 = (s == 0) ? rA0 : ((s == 1) ? rA2 : rA1);
        float A1 = (s == 0) ? rA1 : ((s == 1) ? rA0 : rA2);
        float A2 = (s == 0) ? rA2 : ((s == 1) ? rA1 : rA0);
        float B0 = (s == 0) ? rB0 : ((s == 1) ? rB2 : rB1);
        float B1 = (s == 0) ? rB1 : ((s == 1) ? rB0 : rB2);
        float B2 = (s == 0) ? rB2 : ((s == 1) ? rB1 : rB0);

        #pragma unroll
        for (int off = 16; off > 0; off >>= 1) {
            A0 += __shfl_down_sync(0xffffffffu, A0, off);
            A1 += __shfl_down_sync(0xffffffffu, A1, off);
            A2 += __shfl_down_sync(0xffffffffu, A2, off);
            B0 += __shfl_down_sync(0xffffffffu, B0, off);
            B1 += __shfl_down_sync(0xffffffffu, B1, off);
            B2 += __shfl_down_sync(0xffffffffu, B2, off);
        }

        if (lane == 0)
            out[row] = scale * (A0 * B0 + A1 * B1 + A2 * B2);
    }
}

extern "C" void kernel_launch(void* const* d_in, const int* in_sizes, int n_in,
                              void* d_out, int out_size)
{
    const float* x     = (const float*)d_in[0];
    const float* w_lin = (const float*)d_in[1];
    const float* w_tp  = (const float*)d_in[2];
    float* out = (float*)d_out;

    const int n = in_sizes[0] / ROW_STRIDE_F;          // 200000
    const int rowsPerBlock = 8 * ROWS_PER_WARP;        // 8 warps * 8 rows
    const int blocks = (n + rowsPerBlock - 1) / rowsPerBlock;
    lintp_kernel<<<blocks, 256>>>(x, w_lin, w_tp, out, n);
}